// round 12
// baseline (speedup 1.0000x reference)
#include <cuda_runtime.h>
#include <cuda_fp16.h>
#include <cstdint>
#include <math.h>

#define NCTA 128
#define RS 2056              // W smem row stride (halves)
#define TILEB 4352           // A tile: 16 rows * 136 halves * 2B
#define OFF_HA 197376        // after W (48*2056*2)
#define OFF_YS (OFF_HA + 6*TILEB)   // 223488
#define OFF_XS (OFF_YS + 3264)      // 226752
#define SMEM_SZ (OFF_XS + 64)       // 226816

__device__ __align__(16) __half g_Whi[3u*2048u*2048u];
// W_lo permuted to fragment order: [cta][wid][chunk][nt][lane] as uint2 {b0,b1}
__device__ __align__(16) uint2  g_WloF[128u*16u*16u*3u*32u];
__device__ __align__(16) __half g_h[2][2][16*2048];   // [buf][hi/lo][b*2048+k]
__device__ float g_Xp[2][2048];                        // [buf][cta*16+b]
__device__ __align__(128) unsigned g_flag[NCTA];       // per-CTA generation

__device__ __forceinline__ unsigned su32(const void* p){
    unsigned a;
    asm("{.reg .u64 t; cvta.to.shared.u64 t, %1; cvt.u32.u64 %0, t;}" : "=r"(a) : "l"(p));
    return a;
}
#define CP16(d,s) asm volatile("cp.async.cg.shared.global [%0],[%1],16;\n"::"r"(d),"l"(s))
#define CPC()  asm volatile("cp.async.commit_group;\n")
#define CPW1() asm volatile("cp.async.wait_group 1;\n")
#define CPW0() asm volatile("cp.async.wait_group 0;\n")
#define LDSM4(r0,r1,r2,r3,a) \
    asm volatile("ldmatrix.sync.aligned.m8n8.x4.shared.b16 {%0,%1,%2,%3},[%4];\n" \
        : "=r"(r0),"=r"(r1),"=r"(r2),"=r"(r3) : "r"(a))
#define LDSM2(r0,r1,a) \
    asm volatile("ldmatrix.sync.aligned.m8n8.x2.shared.b16 {%0,%1},[%2];\n" \
        : "=r"(r0),"=r"(r1) : "r"(a))

__device__ __forceinline__ void mma8(float (&d)[4], const unsigned* a, unsigned b0, unsigned b1){
    asm volatile("mma.sync.aligned.m16n8k16.row.col.f32.f16.f16.f32 "
        "{%0,%1,%2,%3},{%4,%5,%6,%7},{%8,%9},{%0,%1,%2,%3};\n"
        : "+f"(d[0]),"+f"(d[1]),"+f"(d[2]),"+f"(d[3])
        : "r"(a[0]),"r"(a[1]),"r"(a[2]),"r"(a[3]),"r"(b0),"r"(b1));
}

__device__ __forceinline__ __half flo(float v){
    __half hi = __float2half_rn(v);
    return __float2half_rn((v - __half2float(hi)) * 2048.f);
}

__global__ void k_init(const float* __restrict__ w_hh, const float* __restrict__ traj_z){
    size_t i = (size_t)blockIdx.x*256 + threadIdx.x;
    if (i < NCTA) g_flag[i] = 0u;
    if (i < 16*2048) {
        float v = traj_z[i];
        __half hi = __float2half_rn(v);
        g_h[0][0][i] = hi;
        g_h[0][1][i] = __float2half_rn((v - __half2float(hi)) * 2048.f);
    }
    for (size_t j = i; j < (size_t)3*2048*2048; j += (size_t)gridDim.x*256){
        g_Whi[j] = __float2half_rn(w_hh[j]);
    }
}

// permute W_lo into per-(cta, warp, chunk, nt, lane) fragment order
__global__ void k_initLo(const float* __restrict__ w_hh){
    unsigned o = blockIdx.x*256 + threadIdx.x;   // 3,145,728 elements
    if (o >= 128u*16u*16u*3u*32u) return;
    unsigned lane = o & 31;
    unsigned nt   = (o >> 5) % 3;
    unsigned c    = (o / 96) & 15;
    unsigned wid  = (o / 1536) & 15;
    unsigned cta  = o / 24576;
    unsigned kw = wid & 7, nh = wid >> 3;
    unsigned g = lane >> 2, tg = lane & 3;
    unsigned rloc = (nh*3 + nt)*8 + g;
    unsigned grow = (rloc >> 4)*2048 + cta*16 + (rloc & 15);
    unsigned ku0 = c*64 + kw*8 + tg;          // unsigned-word index in row
    const float* src = w_hh + (size_t)grow*2048;
    __half l00 = flo(src[2*ku0]),     l01 = flo(src[2*ku0 + 1]);
    __half l10 = flo(src[2*ku0 + 8]), l11 = flo(src[2*ku0 + 9]);   // ku1 = ku0+4
    uint2 v;
    v.x = ((unsigned)__half_as_ushort(l01) << 16) | __half_as_ushort(l00);
    v.y = ((unsigned)__half_as_ushort(l11) << 16) | __half_as_ushort(l10);
    g_WloF[o] = v;
}

__global__ void __launch_bounds__(512,1)
k_gru(const float* __restrict__ traj_z, const float* __restrict__ traj_input,
      const float* __restrict__ w_ih, const float* __restrict__ b_ih,
      const float* __restrict__ b_hh, const float* __restrict__ w_traj,
      const float* __restrict__ b_traj, float* __restrict__ out)
{
    extern __shared__ char sm[];
    __half* Wsm = (__half*)sm;
    char*   HA  = sm + OFF_HA;                 // 6 tiles of 4352B (3 bufs x hi/lo)
    float*  red = (float*)(sm + OFF_HA);       // aliases A tiles: 6 bufs of [48][17]
    float*  Ys  = (float*)(sm + OFF_YS);
    float*  xs  = (float*)(sm + OFF_XS);

    const int tid = threadIdx.x, cta = blockIdx.x, j0 = cta*16;
    const int lane = tid & 31, wid = tid >> 5;
    const int g = lane >> 2, tg = lane & 3;
    const int kw = wid & 7, nh = wid >> 3;     // split-K 8 x split-N 2
    const int ti = tid & 15, tb = tid >> 4;    // gate mapping (tid<256)

    // resident W_hi slice (48 rows x 2048 halves)
    for (int s = tid; s < 48*256; s += 512){
        int r = s >> 8, seg = s & 255;
        int grow = (r >> 4)*2048 + j0 + (r & 15);
        *(int4*)(Wsm + r*RS + seg*8) = *(const int4*)(g_Whi + (size_t)grow*2048 + seg*8);
    }

    float hreg=0, wih0=0,bih0=0,bhh0=0,wih1=0,bih1=0,bhh1=0,wih2=0,bih2=0,bhh2=0,wt=0;
    float bt = b_traj[0];
    if (tid < 256){
        hreg = traj_z[tb*2048 + j0 + ti];
        wih0 = w_ih[j0+ti];      bih0 = b_ih[j0+ti];      bhh0 = b_hh[j0+ti];
        wih1 = w_ih[2048+j0+ti]; bih1 = b_ih[2048+j0+ti]; bhh1 = b_hh[2048+j0+ti];
        wih2 = w_ih[4096+j0+ti]; bih2 = b_ih[4096+j0+ti]; bhh2 = b_hh[4096+j0+ti];
        wt = w_traj[j0+ti];
    }
    if (tid < 16) xs[tid] = traj_input[tid*512];

    const unsigned wB = su32(Wsm), aB = su32(HA);
    const unsigned aOffHi = (unsigned)(((lane&15)*136 + kw*16 + (lane>>4)*8)*2);
    unsigned bRowOff[3];
    #pragma unroll
    for (int nt = 0; nt < 3; nt++){
        int rbase = (nh*3 + nt)*8;
        bRowOff[nt] = (unsigned)(((rbase + (lane&7))*RS + ((lane>>3)&1)*8)*2);
    }
    // fragment-major W_lo pointer: element stride per (c,nt) = 32 uint2
    const uint2* pLoF = g_WloF + ((size_t)(cta*16 + wid))*16*3*32 + lane;
    __syncthreads();

    for (int t = 0; t < 512; t++){
        int p = t & 1;
        const unsigned tgt = (unsigned)t;
        float acc[3][4] = {}, accl[3][4] = {};

        // warp-level producer check: chunk c reads h columns of CTAs 8c..8c+7,
        // published (flag >= t) at the end of those CTAs' step t-1.
        auto waitchunk = [&](int c){
            if (lane < 8){
                const unsigned* fp = g_flag + c*8 + lane;
                unsigned vv;
                do { asm volatile("ld.acquire.gpu.global.u32 %0,[%1];\n"
                                  : "=r"(vv) : "l"(fp)); } while (vv < tgt);
            }
            __syncwarp();
        };
        auto issue = [&](int c){
            int arr = tid >> 8, row = (tid >> 4) & 15, seg = tid & 15;
            unsigned dst = aB + (unsigned)(((c%3)*2 + arr)*TILEB + row*272 + seg*16);
            const __half* src = &g_h[p][arr][row*2048 + c*128 + seg*8];
            CP16(dst, src);
            CPC();
        };
        waitchunk(0); issue(0);
        waitchunk(1); issue(1);

        uint2 bl[3], bln[3];
        #pragma unroll
        for (int nt = 0; nt < 3; nt++) bl[nt] = pLoF[nt*32];

        for (int c = 0; c < 16; c++){
            if (c < 15) CPW1(); else CPW0();
            __syncthreads();
            if (c + 2 < 16){ waitchunk(c + 2); issue(c + 2); }
            if (c < 15){
                #pragma unroll
                for (int nt = 0; nt < 3; nt++) bln[nt] = pLoF[((c+1)*3 + nt)*32];
            }
            unsigned sAh = aB + (unsigned)((c%3)*2*TILEB) + aOffHi;
            unsigned Ahi[4], Alo[4];
            LDSM4(Ahi[0],Ahi[1],Ahi[2],Ahi[3], sAh);
            LDSM4(Alo[0],Alo[1],Alo[2],Alo[3], sAh + TILEB);
            unsigned kg2 = (unsigned)((c*128 + kw*16)*2);
            #pragma unroll
            for (int nt = 0; nt < 3; nt++){
                unsigned b0, b1;
                LDSM2(b0, b1, wB + bRowOff[nt] + kg2);
                mma8(acc[nt],  Ahi, b0, b1);
                mma8(accl[nt], Alo, b0, b1);
                mma8(accl[nt], Ahi, bl[nt].x, bl[nt].y);
            }
            #pragma unroll
            for (int nt = 0; nt < 3; nt++) bl[nt] = bln[nt];
        }

        // combine hi + corrections
        float v[3][4];
        #pragma unroll
        for (int nt = 0; nt < 3; nt++)
            #pragma unroll
            for (int e = 0; e < 4; e++)
                v[nt][e] = acc[nt][e] + accl[nt][e]*(1.f/2048.f);

        auto redst = [&](int b){
            #pragma unroll
            for (int nt = 0; nt < 3; nt++){
                float* d = red + b*816 + ((nh*3+nt)*8 + 2*tg)*17;
                d[g] = v[nt][0]; d[17+g] = v[nt][1]; d[8+g] = v[nt][2]; d[25+g] = v[nt][3];
            }};
        auto redad = [&](int b){
            #pragma unroll
            for (int nt = 0; nt < 3; nt++){
                float* d = red + b*816 + ((nh*3+nt)*8 + 2*tg)*17;
                v[nt][0] += d[g]; v[nt][1] += d[17+g]; v[nt][2] += d[8+g]; v[nt][3] += d[25+g];
            }};

        // red aliases the A-tile SMEM; all warps must finish chunk-15 ldmatrix
        // reads before any warp overwrites that memory with partials.
        __syncthreads();

        if (kw >= 4) redst(kw - 4);
        __syncthreads();
        if (kw < 4) redad(kw);
        if (kw == 2) redst(4);
        if (kw == 3) redst(5);
        __syncthreads();
        if (kw == 0) redad(4);
        if (kw == 1){ redad(5); redst(0); }
        __syncthreads();
        if (kw == 0){
            redad(0);
            #pragma unroll
            for (int nt = 0; nt < 3; nt++){
                float* d = Ys + ((nh*3+nt)*8 + 2*tg)*17;
                d[g] = v[nt][0]; d[17+g] = v[nt][1]; d[8+g] = v[nt][2]; d[25+g] = v[nt][3];
            }
        }
        __syncthreads();

        // deterministic x update: partials of step t-1 are published (all flags
        // >= t verified across this step's 16 chunk checks). warp wid = batch.
        if (t > 0){
            int pp = (t - 1) & 1;
            float s4 = 0.f;
            #pragma unroll
            for (int j2 = 0; j2 < 4; j2++) s4 += g_Xp[pp][(lane + j2*32)*16 + wid];
            s4 += __shfl_xor_sync(0xffffffffu, s4, 16);
            s4 += __shfl_xor_sync(0xffffffffu, s4, 8);
            s4 += __shfl_xor_sync(0xffffffffu, s4, 4);
            s4 += __shfl_xor_sync(0xffffffffu, s4, 2);
            s4 += __shfl_xor_sync(0xffffffffu, s4, 1);
            if (lane == 0){
                float xn = xs[wid] + s4 + bt;
                xs[wid] = xn;
                if (cta == 0) out[wid*512 + (t - 1)] = xn;
            }
        }
        __syncthreads();

        // gate stage (threads 0..255: (ti, tb))
        if (tid < 256){
            float Yr = Ys[ti*17 + tb], Yz = Ys[(16+ti)*17 + tb], Yn = Ys[(32+ti)*17 + tb];
            float x  = xs[tb];
            float r  = 1.f/(1.f + __expf(-(x*wih0 + bih0 + Yr + bhh0)));
            float z  = 1.f/(1.f + __expf(-(x*wih1 + bih1 + Yz + bhh1)));
            float narg = x*wih2 + bih2 + r*(Yn + bhh2);
            float n;
            asm("tanh.approx.f32 %0, %1;\n" : "=f"(n) : "f"(narg));
            hreg = (1.f - z)*n + z*hreg;
            int pn = (t + 1) & 1;
            __half hi = __float2half_rn(hreg);
            g_h[pn][0][tb*2048 + j0 + ti] = hi;
            g_h[pn][1][tb*2048 + j0 + ti] = __float2half_rn((hreg - __half2float(hi))*2048.f);
            float pd = hreg * wt;
            pd += __shfl_xor_sync(0xffffffffu, pd, 1);
            pd += __shfl_xor_sync(0xffffffffu, pd, 2);
            pd += __shfl_xor_sync(0xffffffffu, pd, 4);
            pd += __shfl_xor_sync(0xffffffffu, pd, 8);
            if (ti == 0) g_Xp[p][cta*16 + tb] = pd;
        }
        __syncthreads();
        // publish step t completion (h for t+1 and Xp[t&1] are visible first)
        if (tid == 0){
            asm volatile("st.release.gpu.global.u32 [%0],%1;\n"
                         :: "l"(g_flag + cta), "r"((unsigned)(t + 1)) : "memory");
        }
    }

    // tail: out[.][511] from step-511 partials
    if (cta == 0){
        if (tid < NCTA){
            unsigned vv;
            do { asm volatile("ld.acquire.gpu.global.u32 %0,[%1];\n"
                              : "=r"(vv) : "l"(g_flag + tid)); } while (vv < 512u);
        }
        __syncthreads();
        float s4 = 0.f;
        #pragma unroll
        for (int j2 = 0; j2 < 4; j2++) s4 += g_Xp[1][(lane + j2*32)*16 + wid];
        s4 += __shfl_xor_sync(0xffffffffu, s4, 16);
        s4 += __shfl_xor_sync(0xffffffffu, s4, 8);
        s4 += __shfl_xor_sync(0xffffffffu, s4, 4);
        s4 += __shfl_xor_sync(0xffffffffu, s4, 2);
        s4 += __shfl_xor_sync(0xffffffffu, s4, 1);
        if (lane == 0) out[wid*512 + 511] = xs[wid] + s4 + bt;
    }
}

extern "C" void kernel_launch(void* const* d_in, const int* in_sizes, int n_in,
                              void* d_out, int out_size)
{
    const float* traj_z     = (const float*)d_in[0];
    const float* traj_input = (const float*)d_in[1];
    const float* w_ih       = (const float*)d_in[2];
    const float* b_ih       = (const float*)d_in[3];
    const float* w_hh       = (const float*)d_in[4];
    const float* b_hh       = (const float*)d_in[5];
    const float* w_traj     = (const float*)d_in[6];
    const float* b_traj     = (const float*)d_in[7];
    float* out = (float*)d_out;

    cudaFuncSetAttribute(k_gru, cudaFuncAttributeMaxDynamicSharedMemorySize, SMEM_SZ);
    k_init<<<8192, 256>>>(w_hh, traj_z);
    k_initLo<<<12288, 256>>>(w_hh);
    k_gru<<<NCTA, 512, SMEM_SZ>>>(traj_z, traj_input, w_ih, b_ih, b_hh, w_traj, b_traj, out);
}

// round 14
// speedup vs baseline: 2.6603x; 2.6603x over previous
#include <cuda_runtime.h>
#include <cuda_fp16.h>
#include <cstdint>
#include <math.h>

#define NCTA 128
#define RS 2056              // W smem row stride (halves)
#define TILEB 4352           // A tile: 16 rows * 136 halves * 2B
#define OFF_HA 197376        // after W (48*2056*2)
#define OFF_YS (OFF_HA + 6*TILEB)   // 223488
#define OFF_XS (OFF_YS + 3264)      // 226752
#define SMEM_SZ (OFF_XS + 64)       // 226816

#define LSCALE 8388608.f     // 2^23
#define LINV   (1.f/8388608.f)

__device__ __align__(16) __half g_Whi[3u*2048u*2048u];
// W_lo quantized s8 (scale 2^-23), fragment order: [cta][wid][chunk][nt][lane] = uchar4
__device__ __align__(16) uchar4 g_WloF8[128u*16u*16u*3u*32u];
__device__ __align__(16) __half g_h[2][2][16*2048];   // [buf][hi(x1)/lo(x2^23)][b*2048+k]
__device__ float g_Xp[2][2048];                        // [buf][cta*16+b]
__device__ __align__(128) unsigned g_cnt8[8*32];       // 8 barrier counters, 128B apart

__device__ __forceinline__ unsigned su32(const void* p){
    unsigned a;
    asm("{.reg .u64 t; cvta.to.shared.u64 t, %1; cvt.u32.u64 %0, t;}" : "=r"(a) : "l"(p));
    return a;
}
#define CP16(d,s) asm volatile("cp.async.cg.shared.global [%0],[%1],16;\n"::"r"(d),"l"(s))
#define CPC()  asm volatile("cp.async.commit_group;\n")
#define CPW1() asm volatile("cp.async.wait_group 1;\n")
#define CPW0() asm volatile("cp.async.wait_group 0;\n")
#define LDSM4(r0,r1,r2,r3,a) \
    asm volatile("ldmatrix.sync.aligned.m8n8.x4.shared.b16 {%0,%1,%2,%3},[%4];\n" \
        : "=r"(r0),"=r"(r1),"=r"(r2),"=r"(r3) : "r"(a))
#define LDSM2(r0,r1,a) \
    asm volatile("ldmatrix.sync.aligned.m8n8.x2.shared.b16 {%0,%1},[%2];\n" \
        : "=r"(r0),"=r"(r1) : "r"(a))

__device__ __forceinline__ void mma8(float (&d)[4], const unsigned* a, unsigned b0, unsigned b1){
    asm volatile("mma.sync.aligned.m16n8k16.row.col.f32.f16.f16.f32 "
        "{%0,%1,%2,%3},{%4,%5,%6,%7},{%8,%9},{%0,%1,%2,%3};\n"
        : "+f"(d[0]),"+f"(d[1]),"+f"(d[2]),"+f"(d[3])
        : "r"(a[0]),"r"(a[1]),"r"(a[2]),"r"(a[3]),"r"(b0),"r"(b1));
}

__device__ __forceinline__ unsigned char q8(float w){
    float hi = __half2float(__float2half_rn(w));
    float v = rintf((w - hi) * LSCALE);
    v = fminf(127.f, fmaxf(-127.f, v));
    return (unsigned char)(signed char)(int)v;
}

__global__ void k_init(const float* __restrict__ w_hh, const float* __restrict__ traj_z){
    size_t i = (size_t)blockIdx.x*256 + threadIdx.x;
    if (i < 256) g_cnt8[i] = 0u;
    if (i < 16*2048) {
        float v = traj_z[i];
        __half hi = __float2half_rn(v);
        g_h[0][0][i] = hi;
        g_h[0][1][i] = __float2half_rn((v - __half2float(hi)) * LSCALE);
    }
    for (size_t j = i; j < (size_t)3*2048*2048; j += (size_t)gridDim.x*256){
        g_Whi[j] = __float2half_rn(w_hh[j]);
    }
}

// permute W_lo (s8, scale 2^-23) into per-(cta, warp, chunk, nt, lane) fragment order
__global__ void k_initLo(const float* __restrict__ w_hh){
    unsigned o = blockIdx.x*256 + threadIdx.x;   // 3,145,728 elements
    if (o >= 128u*16u*16u*3u*32u) return;
    unsigned lane = o & 31;
    unsigned nt   = (o >> 5) % 3;
    unsigned c    = (o / 96) & 15;
    unsigned wid  = (o / 1536) & 15;
    unsigned cta  = o / 24576;
    unsigned kw = wid & 7, nh = wid >> 3;
    unsigned g = lane >> 2, tg = lane & 3;
    unsigned rloc = (nh*3 + nt)*8 + g;
    unsigned grow = (rloc >> 4)*2048 + cta*16 + (rloc & 15);
    unsigned ku0 = c*64 + kw*8 + tg;          // 32-bit-word index in row
    const float* src = w_hh + (size_t)grow*2048;
    uchar4 v;
    v.x = q8(src[2*ku0]);     v.y = q8(src[2*ku0 + 1]);
    v.z = q8(src[2*ku0 + 8]); v.w = q8(src[2*ku0 + 9]);   // ku1 = ku0+4
    g_WloF8[o] = v;
}

__global__ void __launch_bounds__(512,1)
k_gru(const float* __restrict__ traj_z, const float* __restrict__ traj_input,
      const float* __restrict__ w_ih, const float* __restrict__ b_ih,
      const float* __restrict__ b_hh, const float* __restrict__ w_traj,
      const float* __restrict__ b_traj, float* __restrict__ out)
{
    extern __shared__ char sm[];
    __half* Wsm = (__half*)sm;
    char*   HA  = sm + OFF_HA;                 // 6 tiles of 4352B (3 bufs x hi/lo)
    float*  red = (float*)(sm + OFF_HA);       // aliases A tiles: 6 bufs of [48][17]
    float*  Ys  = (float*)(sm + OFF_YS);
    float*  xs  = (float*)(sm + OFF_XS);

    const int tid = threadIdx.x, cta = blockIdx.x, j0 = cta*16;
    const int lane = tid & 31, wid = tid >> 5;
    const int g = lane >> 2, tg = lane & 3;
    const int kw = wid & 7, nh = wid >> 3;     // split-K 8 x split-N 2
    const int ti = tid & 15, tb = tid >> 4;    // gate mapping (tid<256)

    // resident W_hi slice (48 rows x 2048 halves)
    for (int s = tid; s < 48*256; s += 512){
        int r = s >> 8, seg = s & 255;
        int grow = (r >> 4)*2048 + j0 + (r & 15);
        *(int4*)(Wsm + r*RS + seg*8) = *(const int4*)(g_Whi + (size_t)grow*2048 + seg*8);
    }

    float hreg=0, wih0=0,bih0=0,bhh0=0,wih1=0,bih1=0,bhh1=0,wih2=0,bih2=0,bhh2=0,wt=0;
    float bt = b_traj[0];
    if (tid < 256){
        hreg = traj_z[tb*2048 + j0 + ti];
        wih0 = w_ih[j0+ti];      bih0 = b_ih[j0+ti];      bhh0 = b_hh[j0+ti];
        wih1 = w_ih[2048+j0+ti]; bih1 = b_ih[2048+j0+ti]; bhh1 = b_hh[2048+j0+ti];
        wih2 = w_ih[4096+j0+ti]; bih2 = b_ih[4096+j0+ti]; bhh2 = b_hh[4096+j0+ti];
        wt = w_traj[j0+ti];
    }
    if (tid < 16) xs[tid] = traj_input[tid*512];

    const unsigned wB = su32(Wsm), aB = su32(HA);
    const unsigned aOffHi = (unsigned)(((lane&15)*136 + kw*16 + (lane>>4)*8)*2);
    unsigned bRowOff[3];
    #pragma unroll
    for (int nt = 0; nt < 3; nt++){
        int rbase = (nh*3 + nt)*8;
        bRowOff[nt] = (unsigned)(((rbase + (lane&7))*RS + ((lane>>3)&1)*8)*2);
    }
    // fragment-major s8 W_lo pointer: element stride per (c,nt) = 32 uchar4
    const uchar4* pLoF = g_WloF8 + ((size_t)(cta*16 + wid))*16*3*32 + lane;
    __syncthreads();

    for (int t = 0; t < 512; t++){
        int p = t & 1;
        float acc[3][4] = {}, accl[3][4] = {};

        auto issue = [&](int c){
            int arr = tid >> 8, row = (tid >> 4) & 15, seg = tid & 15;
            unsigned dst = aB + (unsigned)(((c%3)*2 + arr)*TILEB + row*272 + seg*16);
            const __half* src = &g_h[p][arr][row*2048 + c*128 + seg*8];
            CP16(dst, src);
            CPC();
        };
        issue(0); issue(1);

        // deterministic x update for step t-1 partials (overlaps cp.async).
        // g_Xp[(t-1)&1] was published before the step-(t-1) barrier; nobody
        // rewrites it until gate of step t+1, which is after our barrier t.
        if (t > 0){
            int pp = (t - 1) & 1;
            float s4 = 0.f;
            #pragma unroll
            for (int j2 = 0; j2 < 4; j2++) s4 += g_Xp[pp][(lane + j2*32)*16 + wid];
            s4 += __shfl_xor_sync(0xffffffffu, s4, 16);
            s4 += __shfl_xor_sync(0xffffffffu, s4, 8);
            s4 += __shfl_xor_sync(0xffffffffu, s4, 4);
            s4 += __shfl_xor_sync(0xffffffffu, s4, 2);
            s4 += __shfl_xor_sync(0xffffffffu, s4, 1);
            if (lane == 0){
                float xn = xs[wid] + s4 + bt;
                xs[wid] = xn;
                if (cta == 0) out[wid*512 + (t - 1)] = xn;
            }
        }

        uchar4 bl8[3], bln8[3];
        #pragma unroll
        for (int nt = 0; nt < 3; nt++) bl8[nt] = pLoF[nt*32];

        for (int c = 0; c < 16; c++){
            if (c < 15) CPW1(); else CPW0();
            __syncthreads();
            if (c + 2 < 16) issue(c + 2);
            if (c < 15){
                #pragma unroll
                for (int nt = 0; nt < 3; nt++) bln8[nt] = pLoF[((c+1)*3 + nt)*32];
            }
            unsigned sAh = aB + (unsigned)((c%3)*2*TILEB) + aOffHi;
            unsigned Ahi[4], Alo[4];
            LDSM4(Ahi[0],Ahi[1],Ahi[2],Ahi[3], sAh);
            LDSM4(Alo[0],Alo[1],Alo[2],Alo[3], sAh + TILEB);
            unsigned kg2 = (unsigned)((c*128 + kw*16)*2);
            #pragma unroll
            for (int nt = 0; nt < 3; nt++){
                unsigned b0, b1;
                LDSM2(b0, b1, wB + bRowOff[nt] + kg2);
                // convert s8 W_lo fragment -> fp16x2 (exact: integers <= 127)
                uchar4 q = bl8[nt];
                __half2 p0 = __halves2half2(__short2half_rn((short)(signed char)q.x),
                                            __short2half_rn((short)(signed char)q.y));
                __half2 p1 = __halves2half2(__short2half_rn((short)(signed char)q.z),
                                            __short2half_rn((short)(signed char)q.w));
                unsigned ub0 = *(unsigned*)&p0, ub1 = *(unsigned*)&p1;
                mma8(acc[nt],  Ahi, b0, b1);
                mma8(accl[nt], Alo, b0, b1);
                mma8(accl[nt], Ahi, ub0, ub1);
            }
            #pragma unroll
            for (int nt = 0; nt < 3; nt++) bl8[nt] = bln8[nt];
        }

        // combine hi + corrections (shared 2^-23 scale)
        float v[3][4];
        #pragma unroll
        for (int nt = 0; nt < 3; nt++)
            #pragma unroll
            for (int e = 0; e < 4; e++)
                v[nt][e] = acc[nt][e] + accl[nt][e]*LINV;

        auto redst = [&](int b){
            #pragma unroll
            for (int nt = 0; nt < 3; nt++){
                float* d = red + b*816 + ((nh*3+nt)*8 + 2*tg)*17;
                d[g] = v[nt][0]; d[17+g] = v[nt][1]; d[8+g] = v[nt][2]; d[25+g] = v[nt][3];
            }};
        auto redad = [&](int b){
            #pragma unroll
            for (int nt = 0; nt < 3; nt++){
                float* d = red + b*816 + ((nh*3+nt)*8 + 2*tg)*17;
                v[nt][0] += d[g]; v[nt][1] += d[17+g]; v[nt][2] += d[8+g]; v[nt][3] += d[25+g];
            }};

        // red aliases the A-tile SMEM; all warps must finish chunk-15 ldmatrix
        // reads before any warp overwrites that memory with partials.
        __syncthreads();

        if (kw >= 4) redst(kw - 4);
        __syncthreads();
        if (kw < 4) redad(kw);
        if (kw == 2) redst(4);
        if (kw == 3) redst(5);
        __syncthreads();
        if (kw == 0) redad(4);
        if (kw == 1){ redad(5); redst(0); }
        __syncthreads();
        if (kw == 0){
            redad(0);
            #pragma unroll
            for (int nt = 0; nt < 3; nt++){
                float* d = Ys + ((nh*3+nt)*8 + 2*tg)*17;
                d[g] = v[nt][0]; d[17+g] = v[nt][1]; d[8+g] = v[nt][2]; d[25+g] = v[nt][3];
            }
        }
        __syncthreads();

        // gate stage (threads 0..255: (ti, tb))
        if (tid < 256){
            float Yr = Ys[ti*17 + tb], Yz = Ys[(16+ti)*17 + tb], Yn = Ys[(32+ti)*17 + tb];
            float x  = xs[tb];
            float r  = 1.f/(1.f + __expf(-(x*wih0 + bih0 + Yr + bhh0)));
            float z  = 1.f/(1.f + __expf(-(x*wih1 + bih1 + Yz + bhh1)));
            float narg = x*wih2 + bih2 + r*(Yn + bhh2);
            float n;
            asm("tanh.approx.f32 %0, %1;\n" : "=f"(n) : "f"(narg));
            hreg = (1.f - z)*n + z*hreg;
            int pn = (t + 1) & 1;
            __half hi = __float2half_rn(hreg);
            g_h[pn][0][tb*2048 + j0 + ti] = hi;
            g_h[pn][1][tb*2048 + j0 + ti] = __float2half_rn((hreg - __half2float(hi))*LSCALE);
            float pd = hreg * wt;
            pd += __shfl_xor_sync(0xffffffffu, pd, 1);
            pd += __shfl_xor_sync(0xffffffffu, pd, 2);
            pd += __shfl_xor_sync(0xffffffffu, pd, 4);
            pd += __shfl_xor_sync(0xffffffffu, pd, 8);
            if (ti == 0) g_Xp[p][cta*16 + tb] = pd;
        }
        __syncthreads();
        // distributed barrier: arrive on group counter, 8 lanes poll 8 counters
        {
            const unsigned tgt = 16u*(unsigned)(t + 1);
            if (tid < 8){
                if (tid == 0)
                    asm volatile("red.release.gpu.global.add.u32 [%0],1;\n"
                                 :: "l"(g_cnt8 + (cta >> 4)*32) : "memory");
                unsigned vv;
                const unsigned* cp = g_cnt8 + tid*32;
                do { asm volatile("ld.acquire.gpu.global.u32 %0,[%1];\n"
                                  : "=r"(vv) : "l"(cp)); } while (vv < tgt);
            }
            __syncthreads();
        }
    }

    // tail: out[.][511] from step-511 partials (visible via final barrier)
    if (cta == 0){
        float s4 = 0.f;
        #pragma unroll
        for (int j2 = 0; j2 < 4; j2++) s4 += g_Xp[1][(lane + j2*32)*16 + wid];
        s4 += __shfl_xor_sync(0xffffffffu, s4, 16);
        s4 += __shfl_xor_sync(0xffffffffu, s4, 8);
        s4 += __shfl_xor_sync(0xffffffffu, s4, 4);
        s4 += __shfl_xor_sync(0xffffffffu, s4, 2);
        s4 += __shfl_xor_sync(0xffffffffu, s4, 1);
        if (lane == 0) out[wid*512 + 511] = xs[wid] + s4 + bt;
    }
}

extern "C" void kernel_launch(void* const* d_in, const int* in_sizes, int n_in,
                              void* d_out, int out_size)
{
    const float* traj_z     = (const float*)d_in[0];
    const float* traj_input = (const float*)d_in[1];
    const float* w_ih       = (const float*)d_in[2];
    const float* b_ih       = (const float*)d_in[3];
    const float* w_hh       = (const float*)d_in[4];
    const float* b_hh       = (const float*)d_in[5];
    const float* w_traj     = (const float*)d_in[6];
    const float* b_traj     = (const float*)d_in[7];
    float* out = (float*)d_out;

    cudaFuncSetAttribute(k_gru, cudaFuncAttributeMaxDynamicSharedMemorySize, SMEM_SZ);
    k_init<<<8192, 256>>>(w_hh, traj_z);
    k_initLo<<<12288, 256>>>(w_hh);
    k_gru<<<NCTA, 512, SMEM_SZ>>>(traj_z, traj_input, w_ih, b_ih, b_hh, w_traj, b_traj, out);
}

// round 15
// speedup vs baseline: 2.9161x; 1.0962x over previous
#include <cuda_runtime.h>
#include <cuda_fp16.h>
#include <cstdint>
#include <math.h>

#define NCTA 128
#define RS 2056              // W smem row stride (halves)
#define TILEB 4352           // A tile: 16 rows * 136 halves * 2B
#define OFF_HA 197376        // after W (48*2056*2)
#define OFF_YS (OFF_HA + 6*TILEB)   // 223488
#define OFF_XS (OFF_YS + 3264)      // 226752
#define SMEM_SZ (OFF_XS + 64)       // 226816

__device__ __align__(16) __half g_Whi[3u*2048u*2048u];
// W_lo permuted to fragment order: [cta][wid][chunk][nt][lane] as uint2 {b0,b1}
__device__ __align__(16) uint2  g_WloF[128u*16u*16u*3u*32u];
__device__ __align__(16) __half g_h[2][2][16*2048];   // [buf][hi/lo][b*2048+k]
__device__ float g_Xp[2][2048];                        // [buf][cta*16+b]
__device__ __align__(256) unsigned g_cntA[8*64];       // 8 counters, 256B apart

__device__ __forceinline__ unsigned su32(const void* p){
    unsigned a;
    asm("{.reg .u64 t; cvta.to.shared.u64 t, %1; cvt.u32.u64 %0, t;}" : "=r"(a) : "l"(p));
    return a;
}
#define CP16(d,s) asm volatile("cp.async.cg.shared.global [%0],[%1],16;\n"::"r"(d),"l"(s))
#define CPC()  asm volatile("cp.async.commit_group;\n")
#define CPW1() asm volatile("cp.async.wait_group 1;\n")
#define CPW0() asm volatile("cp.async.wait_group 0;\n")
#define LDSM4(r0,r1,r2,r3,a) \
    asm volatile("ldmatrix.sync.aligned.m8n8.x4.shared.b16 {%0,%1,%2,%3},[%4];\n" \
        : "=r"(r0),"=r"(r1),"=r"(r2),"=r"(r3) : "r"(a))
#define LDSM2(r0,r1,a) \
    asm volatile("ldmatrix.sync.aligned.m8n8.x2.shared.b16 {%0,%1},[%2];\n" \
        : "=r"(r0),"=r"(r1) : "r"(a))

__device__ __forceinline__ void mma8(float (&d)[4], const unsigned* a, unsigned b0, unsigned b1){
    asm volatile("mma.sync.aligned.m16n8k16.row.col.f32.f16.f16.f32 "
        "{%0,%1,%2,%3},{%4,%5,%6,%7},{%8,%9},{%0,%1,%2,%3};\n"
        : "+f"(d[0]),"+f"(d[1]),"+f"(d[2]),"+f"(d[3])
        : "r"(a[0]),"r"(a[1]),"r"(a[2]),"r"(a[3]),"r"(b0),"r"(b1));
}

__device__ __forceinline__ __half flo(float v){
    __half hi = __float2half_rn(v);
    return __float2half_rn((v - __half2float(hi)) * 2048.f);
}

__global__ void k_init(const float* __restrict__ w_hh, const float* __restrict__ traj_z){
    size_t i = (size_t)blockIdx.x*256 + threadIdx.x;
    if (i < 8*64) g_cntA[i] = 0u;
    if (i < 16*2048) {
        float v = traj_z[i];
        __half hi = __float2half_rn(v);
        g_h[0][0][i] = hi;
        g_h[0][1][i] = __float2half_rn((v - __half2float(hi)) * 2048.f);
    }
    for (size_t j = i; j < (size_t)3*2048*2048; j += (size_t)gridDim.x*256){
        g_Whi[j] = __float2half_rn(w_hh[j]);
    }
}

// permute W_lo into per-(cta, warp, chunk, nt, lane) fragment order
__global__ void k_initLo(const float* __restrict__ w_hh){
    unsigned o = blockIdx.x*256 + threadIdx.x;   // 3,145,728 elements
    if (o >= 128u*16u*16u*3u*32u) return;
    unsigned lane = o & 31;
    unsigned nt   = (o >> 5) % 3;
    unsigned c    = (o / 96) & 15;
    unsigned wid  = (o / 1536) & 15;
    unsigned cta  = o / 24576;
    unsigned kw = wid & 7, nh = wid >> 3;
    unsigned g = lane >> 2, tg = lane & 3;
    unsigned rloc = (nh*3 + nt)*8 + g;
    unsigned grow = (rloc >> 4)*2048 + cta*16 + (rloc & 15);
    unsigned ku0 = c*64 + kw*8 + tg;          // 32-bit-word index in row
    const float* src = w_hh + (size_t)grow*2048;
    __half l00 = flo(src[2*ku0]),     l01 = flo(src[2*ku0 + 1]);
    __half l10 = flo(src[2*ku0 + 8]), l11 = flo(src[2*ku0 + 9]);   // ku1 = ku0+4
    uint2 v;
    v.x = ((unsigned)__half_as_ushort(l01) << 16) | __half_as_ushort(l00);
    v.y = ((unsigned)__half_as_ushort(l11) << 16) | __half_as_ushort(l10);
    g_WloF[o] = v;
}

__global__ void __launch_bounds__(512,1)
k_gru(const float* __restrict__ traj_z, const float* __restrict__ traj_input,
      const float* __restrict__ w_ih, const float* __restrict__ b_ih,
      const float* __restrict__ b_hh, const float* __restrict__ w_traj,
      const float* __restrict__ b_traj, float* __restrict__ out)
{
    extern __shared__ char sm[];
    __half* Wsm = (__half*)sm;
    char*   HA  = sm + OFF_HA;                 // 6 tiles of 4352B (3 bufs x hi/lo)
    float*  red = (float*)(sm + OFF_HA);       // aliases A tiles: 6 bufs of [48][17]
    float*  Ys  = (float*)(sm + OFF_YS);
    float*  xs  = (float*)(sm + OFF_XS);

    const int tid = threadIdx.x, cta = blockIdx.x, j0 = cta*16;
    const int lane = tid & 31, wid = tid >> 5;
    const int g = lane >> 2, tg = lane & 3;
    const int kw = wid & 7, nh = wid >> 3;     // split-K 8 x split-N 2
    const int ti = tid & 15, tb = tid >> 4;    // gate mapping (tid<256)

    // resident W_hi slice (48 rows x 2048 halves)
    for (int s = tid; s < 48*256; s += 512){
        int r = s >> 8, seg = s & 255;
        int grow = (r >> 4)*2048 + j0 + (r & 15);
        *(int4*)(Wsm + r*RS + seg*8) = *(const int4*)(g_Whi + (size_t)grow*2048 + seg*8);
    }

    float hreg=0, wih0=0,bih0=0,bhh0=0,wih1=0,bih1=0,bhh1=0,wih2=0,bih2=0,bhh2=0,wt=0;
    float bt = b_traj[0];
    if (tid < 256){
        hreg = traj_z[tb*2048 + j0 + ti];
        wih0 = w_ih[j0+ti];      bih0 = b_ih[j0+ti];      bhh0 = b_hh[j0+ti];
        wih1 = w_ih[2048+j0+ti]; bih1 = b_ih[2048+j0+ti]; bhh1 = b_hh[2048+j0+ti];
        wih2 = w_ih[4096+j0+ti]; bih2 = b_ih[4096+j0+ti]; bhh2 = b_hh[4096+j0+ti];
        wt = w_traj[j0+ti];
    }
    if (tid < 16) xs[tid] = traj_input[tid*512];

    const unsigned wB = su32(Wsm), aB = su32(HA);
    const unsigned aOffHi = (unsigned)(((lane&15)*136 + kw*16 + (lane>>4)*8)*2);
    unsigned bRowOff[3];
    #pragma unroll
    for (int nt = 0; nt < 3; nt++){
        int rbase = (nh*3 + nt)*8;
        bRowOff[nt] = (unsigned)(((rbase + (lane&7))*RS + ((lane>>3)&1)*8)*2);
    }
    // fragment-major W_lo pointer: element stride per (c,nt) = 32 uint2
    const uint2* pLoF = g_WloF + ((size_t)(cta*16 + wid))*16*3*32 + lane;
    __syncthreads();

    for (int t = 0; t < 512; t++){
        int p = t & 1;
        float acc[3][4] = {}, accl[3][4] = {};

        auto issue = [&](int c){
            int arr = tid >> 8, row = (tid >> 4) & 15, seg = tid & 15;
            unsigned dst = aB + (unsigned)(((c%3)*2 + arr)*TILEB + row*272 + seg*16);
            const __half* src = &g_h[p][arr][row*2048 + c*128 + seg*8];
            CP16(dst, src);
            CPC();
        };
        issue(0); issue(1);

        // deterministic x update for step t-1 (overlaps cp.async).
        // g_Xp[(t-1)&1] was written before barrier t-1 (release) and is not
        // rewritten until gate of step t+1, which is after barrier t — and our
        // read precedes our arrival at barrier t. Race-free.
        if (t > 0){
            int pp = (t - 1) & 1;
            float s4 = 0.f;
            #pragma unroll
            for (int j2 = 0; j2 < 4; j2++) s4 += g_Xp[pp][(lane + j2*32)*16 + wid];
            s4 += __shfl_xor_sync(0xffffffffu, s4, 16);
            s4 += __shfl_xor_sync(0xffffffffu, s4, 8);
            s4 += __shfl_xor_sync(0xffffffffu, s4, 4);
            s4 += __shfl_xor_sync(0xffffffffu, s4, 2);
            s4 += __shfl_xor_sync(0xffffffffu, s4, 1);
            if (lane == 0){
                float xn = xs[wid] + s4 + bt;
                xs[wid] = xn;
                if (cta == 0) out[wid*512 + (t - 1)] = xn;
            }
        }

        uint2 bl[3], bln[3];
        #pragma unroll
        for (int nt = 0; nt < 3; nt++) bl[nt] = pLoF[nt*32];

        for (int c = 0; c < 16; c++){
            if (c < 15) CPW1(); else CPW0();
            __syncthreads();
            if (c + 2 < 16) issue(c + 2);
            if (c < 15){
                #pragma unroll
                for (int nt = 0; nt < 3; nt++) bln[nt] = pLoF[((c+1)*3 + nt)*32];
            }
            unsigned sAh = aB + (unsigned)((c%3)*2*TILEB) + aOffHi;
            unsigned Ahi[4], Alo[4];
            LDSM4(Ahi[0],Ahi[1],Ahi[2],Ahi[3], sAh);
            LDSM4(Alo[0],Alo[1],Alo[2],Alo[3], sAh + TILEB);
            unsigned kg2 = (unsigned)((c*128 + kw*16)*2);
            #pragma unroll
            for (int nt = 0; nt < 3; nt++){
                unsigned b0, b1;
                LDSM2(b0, b1, wB + bRowOff[nt] + kg2);
                mma8(acc[nt],  Ahi, b0, b1);
                mma8(accl[nt], Alo, b0, b1);
                mma8(accl[nt], Ahi, bl[nt].x, bl[nt].y);
            }
            #pragma unroll
            for (int nt = 0; nt < 3; nt++) bl[nt] = bln[nt];
        }

        // combine hi + corrections
        float v[3][4];
        #pragma unroll
        for (int nt = 0; nt < 3; nt++)
            #pragma unroll
            for (int e = 0; e < 4; e++)
                v[nt][e] = acc[nt][e] + accl[nt][e]*(1.f/2048.f);

        auto redst = [&](int b){
            #pragma unroll
            for (int nt = 0; nt < 3; nt++){
                float* d = red + b*816 + ((nh*3+nt)*8 + 2*tg)*17;
                d[g] = v[nt][0]; d[17+g] = v[nt][1]; d[8+g] = v[nt][2]; d[25+g] = v[nt][3];
            }};
        auto redad = [&](int b){
            #pragma unroll
            for (int nt = 0; nt < 3; nt++){
                float* d = red + b*816 + ((nh*3+nt)*8 + 2*tg)*17;
                v[nt][0] += d[g]; v[nt][1] += d[17+g]; v[nt][2] += d[8+g]; v[nt][3] += d[25+g];
            }};

        // red aliases the A-tile SMEM; all warps must finish chunk-15 ldmatrix
        // reads before any warp overwrites that memory with partials.
        __syncthreads();

        if (kw >= 4) redst(kw - 4);
        __syncthreads();
        if (kw < 4) redad(kw);
        if (kw == 2) redst(4);
        if (kw == 3) redst(5);
        __syncthreads();
        if (kw == 0) redad(4);
        if (kw == 1){ redad(5); redst(0); }
        __syncthreads();
        if (kw == 0){
            redad(0);
            #pragma unroll
            for (int nt = 0; nt < 3; nt++){
                float* d = Ys + ((nh*3+nt)*8 + 2*tg)*17;
                d[g] = v[nt][0]; d[17+g] = v[nt][1]; d[8+g] = v[nt][2]; d[25+g] = v[nt][3];
            }
        }
        __syncthreads();

        // gate stage (threads 0..255: (ti, tb))
        if (tid < 256){
            float Yr = Ys[ti*17 + tb], Yz = Ys[(16+ti)*17 + tb], Yn = Ys[(32+ti)*17 + tb];
            float x  = xs[tb];
            float r  = 1.f/(1.f + __expf(-(x*wih0 + bih0 + Yr + bhh0)));
            float z  = 1.f/(1.f + __expf(-(x*wih1 + bih1 + Yz + bhh1)));
            float narg = x*wih2 + bih2 + r*(Yn + bhh2);
            float n;
            asm("tanh.approx.f32 %0, %1;\n" : "=f"(n) : "f"(narg));
            hreg = (1.f - z)*n + z*hreg;
            int pn = (t + 1) & 1;
            __half hi = __float2half_rn(hreg);
            g_h[pn][0][tb*2048 + j0 + ti] = hi;
            g_h[pn][1][tb*2048 + j0 + ti] = __float2half_rn((hreg - __half2float(hi))*2048.f);
            float pd = hreg * wt;
            pd += __shfl_xor_sync(0xffffffffu, pd, 1);
            pd += __shfl_xor_sync(0xffffffffu, pd, 2);
            pd += __shfl_xor_sync(0xffffffffu, pd, 4);
            pd += __shfl_xor_sync(0xffffffffu, pd, 8);
            if (ti == 0) g_Xp[p][cta*16 + tb] = pd;
        }
        __syncthreads();
        // distributed barrier: arrive on counter (cta&7), 256B-spaced counters
        // land on distinct L2 slices (bit 8 differs). 16 arrivals/counter.
        {
            const unsigned tgt = 16u*(unsigned)(t + 1);
            if (tid == 0)
                asm volatile("red.release.gpu.global.add.u32 [%0],1;\n"
                             :: "l"(g_cntA + (cta & 7)*64) : "memory");
            if (tid < 8){
                unsigned vv;
                const unsigned* cp2 = g_cntA + tid*64;
                do { asm volatile("ld.acquire.gpu.global.u32 %0,[%1];\n"
                                  : "=r"(vv) : "l"(cp2)); } while (vv < tgt);
            }
            __syncthreads();
        }
    }

    // tail: out[.][511] from step-511 partials (visible via final barrier)
    if (cta == 0){
        float s4 = 0.f;
        #pragma unroll
        for (int j2 = 0; j2 < 4; j2++) s4 += g_Xp[1][(lane + j2*32)*16 + wid];
        s4 += __shfl_xor_sync(0xffffffffu, s4, 16);
        s4 += __shfl_xor_sync(0xffffffffu, s4, 8);
        s4 += __shfl_xor_sync(0xffffffffu, s4, 4);
        s4 += __shfl_xor_sync(0xffffffffu, s4, 2);
        s4 += __shfl_xor_sync(0xffffffffu, s4, 1);
        if (lane == 0) out[wid*512 + 511] = xs[wid] + s4 + bt;
    }
}

extern "C" void kernel_launch(void* const* d_in, const int* in_sizes, int n_in,
                              void* d_out, int out_size)
{
    const float* traj_z     = (const float*)d_in[0];
    const float* traj_input = (const float*)d_in[1];
    const float* w_ih       = (const float*)d_in[2];
    const float* b_ih       = (const float*)d_in[3];
    const float* w_hh       = (const float*)d_in[4];
    const float* b_hh       = (const float*)d_in[5];
    const float* w_traj     = (const float*)d_in[6];
    const float* b_traj     = (const float*)d_in[7];
    float* out = (float*)d_out;

    cudaFuncSetAttribute(k_gru, cudaFuncAttributeMaxDynamicSharedMemorySize, SMEM_SZ);
    k_init<<<8192, 256>>>(w_hh, traj_z);
    k_initLo<<<12288, 256>>>(w_hh);
    k_gru<<<NCTA, 512, SMEM_SZ>>>(traj_z, traj_input, w_ih, b_ih, b_hh, w_traj, b_traj, out);
}